// round 1
// baseline (speedup 1.0000x reference)
#include <cuda_runtime.h>
#include <cuda_bf16.h>
#include <math.h>

#define Bb 8
#define Nn 16384
#define Dd 768
#define Rr 3
#define NE 4
#define Hh 128

// Scratch (allocation-free rule: __device__ globals)
__device__ float g_xr[Bb * Rr * Nn];     // (B,R,N): doubles as NCHW image (b,r,h,w)
__device__ float g_xa[Bb * Rr];
__device__ float g_G[Bb * NE];
__device__ float g_mixed[Bb * Rr * Nn];  // (B,R,N)

// ---------------------------------------------------------------------------
// Kernel 1: xr = x @ Wd + bd.  Warp per row, Wd in smem, float4 loads.
// grid = B*N/8 blocks of 256 threads (8 warps/block).
// ---------------------------------------------------------------------------
__global__ void k_proj_down(const float* __restrict__ x,
                            const float* __restrict__ Wd,
                            const float* __restrict__ bd) {
    __shared__ float sWd[Dd * Rr];
    int tid = threadIdx.x;
    for (int i = tid; i < Dd * Rr; i += blockDim.x) sWd[i] = Wd[i];
    __syncthreads();

    int warp = tid >> 5, lane = tid & 31;
    int row = blockIdx.x * 8 + warp;              // [0, B*N)
    const float4* xr4 = (const float4*)(x + (long long)row * Dd);

    float a0 = 0.f, a1 = 0.f, a2 = 0.f;
#pragma unroll
    for (int k = 0; k < 6; k++) {
        int f4i = lane + 32 * k;                  // 192 float4 per row
        float4 v = xr4[f4i];
        int d0 = f4i * 4;
        const float* w = &sWd[d0 * 3];
        a0 += v.x * w[0] + v.y * w[3] + v.z * w[6] + v.w * w[9];
        a1 += v.x * w[1] + v.y * w[4] + v.z * w[7] + v.w * w[10];
        a2 += v.x * w[2] + v.y * w[5] + v.z * w[8] + v.w * w[11];
    }
#pragma unroll
    for (int off = 16; off > 0; off >>= 1) {
        a0 += __shfl_down_sync(0xffffffffu, a0, off);
        a1 += __shfl_down_sync(0xffffffffu, a1, off);
        a2 += __shfl_down_sync(0xffffffffu, a2, off);
    }
    if (lane == 0) {
        int b = row >> 14, n = row & (Nn - 1);
        g_xr[((long long)b * Rr + 0) * Nn + n] = a0 + bd[0];
        g_xr[((long long)b * Rr + 1) * Nn + n] = a1 + bd[1];
        g_xr[((long long)b * Rr + 2) * Nn + n] = a2 + bd[2];
    }
}

// ---------------------------------------------------------------------------
// Kernel 2: xa[b,r] = mean_n xr[b,n,r].  Deterministic tree reduction.
// grid = B*R blocks of 256 threads.
// ---------------------------------------------------------------------------
__global__ void k_mean() {
    __shared__ float s[256];
    int br = blockIdx.x;
    const float* p = g_xr + (long long)br * Nn;
    float a = 0.f;
    for (int i = threadIdx.x; i < Nn; i += 256) a += p[i];
    s[threadIdx.x] = a;
    __syncthreads();
    for (int off = 128; off > 0; off >>= 1) {
        if (threadIdx.x < off) s[threadIdx.x] += s[threadIdx.x + off];
        __syncthreads();
    }
    if (threadIdx.x == 0) g_xa[br] = s[0] * (1.0f / (float)Nn);
}

// ---------------------------------------------------------------------------
// Kernel 3: gating.  One thread per batch.
// ---------------------------------------------------------------------------
__global__ void k_gate(const float* __restrict__ noise,
                       const float* __restrict__ Wg,
                       const float* __restrict__ Wn) {
    int b = threadIdx.x;
    if (b >= Bb) return;
    float xa0 = g_xa[b * 3 + 0], xa1 = g_xa[b * 3 + 1], xa2 = g_xa[b * 3 + 2];
    float hl[NE];
#pragma unroll
    for (int e = 0; e < NE; e++) {
        float hg = xa0 * Wg[0 * NE + e] + xa1 * Wg[1 * NE + e] + xa2 * Wg[2 * NE + e];
        float hn = xa0 * Wn[0 * NE + e] + xa1 * Wn[1 * NE + e] + xa2 * Wn[2 * NE + e];
        float sp = (hn > 0.f) ? hn + log1pf(expf(-hn)) : log1pf(expf(hn));
        hl[e] = hg + noise[b * NE + e] * sp;
    }
    // top-2 (ties -> lower index, matching lax.top_k)
    int i1 = 0;
#pragma unroll
    for (int e = 1; e < NE; e++) if (hl[e] > hl[i1]) i1 = e;
    int i2 = -1;
#pragma unroll
    for (int e = 0; e < NE; e++) {
        if (e == i1) continue;
        if (i2 < 0 || hl[e] > hl[i2]) i2 = e;
    }
    float e2 = expf(hl[i2] - hl[i1]);
    float inv = 1.0f / (1.0f + e2);
    float g[NE] = {0.f, 0.f, 0.f, 0.f};
    g[i1] = inv;
    g[i2] = e2 * inv;
#pragma unroll
    for (int e = 0; e < NE; e++) g_G[b * NE + e] = g[e];
}

// ---------------------------------------------------------------------------
// Kernel 4: expert pyramid.  One block per (b,r) image, 256 threads.
// ---------------------------------------------------------------------------
__device__ __forceinline__ void conv3x3_smem(const float* __restrict__ in,
                                             float* __restrict__ out, int S,
                                             const float* k9, float kb,
                                             int t, int nt) {
    for (int i = t; i < S * S; i += nt) {
        int y = i / S, x = i - y * S;
        float v = kb;
#pragma unroll
        for (int ky = 0; ky < 3; ky++) {
            int yy = y + ky - 1;
            if (yy < 0 || yy >= S) continue;
#pragma unroll
            for (int kx = 0; kx < 3; kx++) {
                int xx = x + kx - 1;
                if (xx < 0 || xx >= S) continue;
                v += in[yy * S + xx] * k9[ky * 3 + kx];
            }
        }
        out[i] = v;
    }
}

__device__ __forceinline__ float up_bilin(const float* __restrict__ c, int S,
                                          int y, int x, float a, float off) {
    float py = a * (float)y + off;
    float px = a * (float)x + off;
    float fy = floorf(py), fx = floorf(px);
    float wy = py - fy, wx = px - fx;
    int y0 = (int)fy, x0 = (int)fx;
    int y1 = y0 + 1, x1 = x0 + 1;
    y0 = max(0, min(S - 1, y0)); y1 = max(0, min(S - 1, y1));
    x0 = max(0, min(S - 1, x0)); x1 = max(0, min(S - 1, x1));
    float v00 = c[y0 * S + x0], v01 = c[y0 * S + x1];
    float v10 = c[y1 * S + x0], v11 = c[y1 * S + x1];
    float v0 = v00 + wx * (v01 - v00);
    float v1 = v10 + wx * (v11 - v10);
    return v0 + wy * (v1 - v0);
}

__global__ void k_experts(const float* __restrict__ dwk,
                          const float* __restrict__ dwb) {
    __shared__ float d64[64 * 64], c64[64 * 64];
    __shared__ float d32[32 * 32], c32[32 * 32];
    __shared__ float d16[16 * 16], c16[16 * 16];

    int br = blockIdx.x;
    int b = br / Rr, r = br - b * Rr;
    const float* img = g_xr + (long long)br * Nn;   // 128x128
    float* outp = g_mixed + (long long)br * Nn;

    float k9[9];
#pragma unroll
    for (int i = 0; i < 9; i++) k9[i] = dwk[r * 9 + i];
    float kb = dwb[r];

    int t = threadIdx.x;
    // direct downsamples from the 128x128 image (half-pixel, antialias=False)
    for (int i = t; i < 64 * 64; i += 256) {
        int y = i >> 6, x = i & 63;
        const float* p0 = img + (2 * y) * 128 + 2 * x;
        d64[i] = 0.25f * (p0[0] + p0[1] + p0[128] + p0[129]);
    }
    for (int i = t; i < 32 * 32; i += 256) {
        int y = i >> 5, x = i & 31;
        const float* p0 = img + (4 * y + 1) * 128 + 4 * x + 1;
        d32[i] = 0.25f * (p0[0] + p0[1] + p0[128] + p0[129]);
    }
    for (int i = t; i < 16 * 16; i += 256) {
        int y = i >> 4, x = i & 15;
        const float* p0 = img + (8 * y + 3) * 128 + 8 * x + 3;
        d16[i] = 0.25f * (p0[0] + p0[1] + p0[128] + p0[129]);
    }
    __syncthreads();
    conv3x3_smem(d64, c64, 64, k9, kb, t, 256);
    conv3x3_smem(d32, c32, 32, k9, kb, t, 256);
    conv3x3_smem(d16, c16, 16, k9, kb, t, 256);
    __syncthreads();

    float G0 = g_G[b * NE + 0], G1 = g_G[b * NE + 1];
    float G2 = g_G[b * NE + 2], G3 = g_G[b * NE + 3];

    for (int p = t; p < Nn; p += 256) {
        int y = p >> 7, x = p & 127;
        // scale 1.0: conv directly on the full-res image (zero padding)
        float v = kb;
#pragma unroll
        for (int ky = 0; ky < 3; ky++) {
            int yy = y + ky - 1;
            if (yy < 0 || yy >= 128) continue;
#pragma unroll
            for (int kx = 0; kx < 3; kx++) {
                int xx = x + kx - 1;
                if (xx < 0 || xx >= 128) continue;
                v += img[yy * 128 + xx] * k9[ky * 3 + kx];
            }
        }
        float u1 = up_bilin(c64, 64, y, x, 0.5f,   -0.25f);
        float u2 = up_bilin(c32, 32, y, x, 0.25f,  -0.375f);
        float u3 = up_bilin(c16, 16, y, x, 0.125f, -0.4375f);
        outp[p] = G0 * v + G1 * u1 + G2 * u2 + G3 * u3;
    }
}

// ---------------------------------------------------------------------------
// Kernel 5: out = x + mixed @ Wu + bu.  192 threads = one row of float4;
// 8 rows per block so Wu/bu stay in registers.
// ---------------------------------------------------------------------------
__global__ void k_out(const float* __restrict__ x,
                      const float* __restrict__ Wu,
                      const float* __restrict__ bu,
                      float* __restrict__ out) {
    int t = threadIdx.x;  // 0..191
    const float4* Wu4 = (const float4*)Wu;
    float4 w0 = Wu4[t], w1 = Wu4[192 + t], w2 = Wu4[384 + t];
    float4 bv = ((const float4*)bu)[t];

    long long row0 = (long long)blockIdx.x * 8;
#pragma unroll
    for (int i = 0; i < 8; i++) {
        long long row = row0 + i;
        int b = (int)(row >> 14), n = (int)(row & (Nn - 1));
        float m0 = g_mixed[((long long)b * Rr + 0) * Nn + n];
        float m1 = g_mixed[((long long)b * Rr + 1) * Nn + n];
        float m2 = g_mixed[((long long)b * Rr + 2) * Nn + n];
        float4 xv = ((const float4*)(x + row * Dd))[t];
        float4 rv;
        rv.x = xv.x + m0 * w0.x + m1 * w1.x + m2 * w2.x + bv.x;
        rv.y = xv.y + m0 * w0.y + m1 * w1.y + m2 * w2.y + bv.y;
        rv.z = xv.z + m0 * w0.z + m1 * w1.z + m2 * w2.z + bv.z;
        rv.w = xv.w + m0 * w0.w + m1 * w1.w + m2 * w2.w + bv.w;
        ((float4*)out)[row * 192 + t] = rv;
    }
}

// ---------------------------------------------------------------------------
extern "C" void kernel_launch(void* const* d_in, const int* in_sizes, int n_in,
                              void* d_out, int out_size) {
    const float* x     = (const float*)d_in[0];
    const float* noise = (const float*)d_in[1];
    const float* Wd    = (const float*)d_in[2];
    const float* bd    = (const float*)d_in[3];
    const float* Wu    = (const float*)d_in[4];
    const float* bu    = (const float*)d_in[5];
    const float* Wg    = (const float*)d_in[6];
    const float* Wn    = (const float*)d_in[7];
    const float* dwk   = (const float*)d_in[8];
    const float* dwb   = (const float*)d_in[9];
    float* out = (float*)d_out;

    k_proj_down<<<(Bb * Nn) / 8, 256>>>(x, Wd, bd);
    k_mean<<<Bb * Rr, 256>>>();
    k_gate<<<1, 32>>>(noise, Wg, Wn);
    k_experts<<<Bb * Rr, 256>>>(dwk, dwb);
    k_out<<<(Bb * Nn) / 8, 192>>>(x, Wu, bu, out);
}

// round 2
// speedup vs baseline: 1.0796x; 1.0796x over previous
#include <cuda_runtime.h>
#include <cuda_bf16.h>
#include <math.h>

#define Bb 8
#define Nn 16384
#define Dd 768
#define Rr 3
#define NE 4
#define Hh 128

// Scratch (allocation-free rule: __device__ globals)
__device__ float g_xr[Bb * Rr * Nn];     // (B,R,N): doubles as NCHW image (b,r,h,w)
__device__ float g_xa[Bb * Rr];
__device__ float g_G[Bb * NE];
__device__ float g_mixed[Bb * Rr * Nn];  // (B,R,N)
__device__ float g_c64[Bb * Rr * 64 * 64];
__device__ float g_c32[Bb * Rr * 32 * 32];
__device__ float g_c16[Bb * Rr * 16 * 16];

// ---------------------------------------------------------------------------
// Kernel 1: xr = x @ Wd + bd.  Warp per row, Wd in smem, float4 loads.
// grid = B*N/8 blocks of 256 threads (8 warps/block).
// ---------------------------------------------------------------------------
__global__ void k_proj_down(const float* __restrict__ x,
                            const float* __restrict__ Wd,
                            const float* __restrict__ bd) {
    __shared__ float sWd[Dd * Rr];
    int tid = threadIdx.x;
    for (int i = tid; i < Dd * Rr; i += blockDim.x) sWd[i] = Wd[i];
    __syncthreads();

    int warp = tid >> 5, lane = tid & 31;
    int row = blockIdx.x * 8 + warp;              // [0, B*N)
    const float4* xr4 = (const float4*)(x + (long long)row * Dd);

    float a0 = 0.f, a1 = 0.f, a2 = 0.f;
#pragma unroll
    for (int k = 0; k < 6; k++) {
        int f4i = lane + 32 * k;                  // 192 float4 per row
        float4 v = xr4[f4i];
        int d0 = f4i * 4;
        const float* w = &sWd[d0 * 3];
        a0 += v.x * w[0] + v.y * w[3] + v.z * w[6] + v.w * w[9];
        a1 += v.x * w[1] + v.y * w[4] + v.z * w[7] + v.w * w[10];
        a2 += v.x * w[2] + v.y * w[5] + v.z * w[8] + v.w * w[11];
    }
#pragma unroll
    for (int off = 16; off > 0; off >>= 1) {
        a0 += __shfl_down_sync(0xffffffffu, a0, off);
        a1 += __shfl_down_sync(0xffffffffu, a1, off);
        a2 += __shfl_down_sync(0xffffffffu, a2, off);
    }
    if (lane == 0) {
        int b = row >> 14, n = row & (Nn - 1);
        g_xr[((long long)b * Rr + 0) * Nn + n] = a0 + bd[0];
        g_xr[((long long)b * Rr + 1) * Nn + n] = a1 + bd[1];
        g_xr[((long long)b * Rr + 2) * Nn + n] = a2 + bd[2];
    }
}

// ---------------------------------------------------------------------------
// Kernel 2: xa[b,r] = mean_n xr[b,n,r].  Deterministic tree reduction.
// ---------------------------------------------------------------------------
__global__ void k_mean() {
    __shared__ float s[256];
    int br = blockIdx.x;
    const float* p = g_xr + (long long)br * Nn;
    float a = 0.f;
    for (int i = threadIdx.x; i < Nn; i += 256) a += p[i];
    s[threadIdx.x] = a;
    __syncthreads();
    for (int off = 128; off > 0; off >>= 1) {
        if (threadIdx.x < off) s[threadIdx.x] += s[threadIdx.x + off];
        __syncthreads();
    }
    if (threadIdx.x == 0) g_xa[br] = s[0] * (1.0f / (float)Nn);
}

// ---------------------------------------------------------------------------
// Kernel 3: gating.  One thread per batch.
// ---------------------------------------------------------------------------
__global__ void k_gate(const float* __restrict__ noise,
                       const float* __restrict__ Wg,
                       const float* __restrict__ Wn) {
    int b = threadIdx.x;
    if (b >= Bb) return;
    float xa0 = g_xa[b * 3 + 0], xa1 = g_xa[b * 3 + 1], xa2 = g_xa[b * 3 + 2];
    float hl[NE];
#pragma unroll
    for (int e = 0; e < NE; e++) {
        float hg = xa0 * Wg[0 * NE + e] + xa1 * Wg[1 * NE + e] + xa2 * Wg[2 * NE + e];
        float hn = xa0 * Wn[0 * NE + e] + xa1 * Wn[1 * NE + e] + xa2 * Wn[2 * NE + e];
        float sp = (hn > 0.f) ? hn + log1pf(expf(-hn)) : log1pf(expf(hn));
        hl[e] = hg + noise[b * NE + e] * sp;
    }
    int i1 = 0;
#pragma unroll
    for (int e = 1; e < NE; e++) if (hl[e] > hl[i1]) i1 = e;
    int i2 = -1;
#pragma unroll
    for (int e = 0; e < NE; e++) {
        if (e == i1) continue;
        if (i2 < 0 || hl[e] > hl[i2]) i2 = e;
    }
    float e2 = expf(hl[i2] - hl[i1]);
    float inv = 1.0f / (1.0f + e2);
    float g[NE] = {0.f, 0.f, 0.f, 0.f};
    g[i1] = inv;
    g[i2] = e2 * inv;
#pragma unroll
    for (int e = 0; e < NE; e++) g_G[b * NE + e] = g[e];
}

// ---------------------------------------------------------------------------
// Kernel 4a: small-scale pyramid.  One block per (b,r); downsample + conv at
// 64/32/16, results to L2-resident global scratch.
// ---------------------------------------------------------------------------
__device__ __forceinline__ void conv3x3_g(const float* __restrict__ in,
                                          float* __restrict__ out, int S,
                                          const float* k9, float kb,
                                          int t, int nt) {
    for (int i = t; i < S * S; i += nt) {
        int y = i / S, x = i - y * S;
        float v = kb;
#pragma unroll
        for (int ky = 0; ky < 3; ky++) {
            int yy = y + ky - 1;
            if (yy < 0 || yy >= S) continue;
#pragma unroll
            for (int kx = 0; kx < 3; kx++) {
                int xx = x + kx - 1;
                if (xx < 0 || xx >= S) continue;
                v += in[yy * S + xx] * k9[ky * 3 + kx];
            }
        }
        out[i] = v;
    }
}

__global__ void k_pyramid(const float* __restrict__ dwk,
                          const float* __restrict__ dwb) {
    __shared__ float d64[64 * 64];
    __shared__ float d32[32 * 32];
    __shared__ float d16[16 * 16];

    int br = blockIdx.x;
    int r = br % Rr;
    const float* img = g_xr + (long long)br * Nn;   // 128x128

    float k9[9];
#pragma unroll
    for (int i = 0; i < 9; i++) k9[i] = dwk[r * 9 + i];
    float kb = dwb[r];

    int t = threadIdx.x;
    // direct downsamples from the 128x128 image (half-pixel, antialias=False)
    for (int i = t; i < 64 * 64; i += 256) {
        int y = i >> 6, x = i & 63;
        const float* p0 = img + (2 * y) * 128 + 2 * x;
        d64[i] = 0.25f * (p0[0] + p0[1] + p0[128] + p0[129]);
    }
    for (int i = t; i < 32 * 32; i += 256) {
        int y = i >> 5, x = i & 31;
        const float* p0 = img + (4 * y + 1) * 128 + 4 * x + 1;
        d32[i] = 0.25f * (p0[0] + p0[1] + p0[128] + p0[129]);
    }
    for (int i = t; i < 16 * 16; i += 256) {
        int y = i >> 4, x = i & 15;
        const float* p0 = img + (8 * y + 3) * 128 + 8 * x + 3;
        d16[i] = 0.25f * (p0[0] + p0[1] + p0[128] + p0[129]);
    }
    __syncthreads();
    conv3x3_g(d64, g_c64 + br * 64 * 64, 64, k9, kb, t, 256);
    conv3x3_g(d32, g_c32 + br * 32 * 32, 32, k9, kb, t, 256);
    conv3x3_g(d16, g_c16 + br * 16 * 16, 16, k9, kb, t, 256);
}

// ---------------------------------------------------------------------------
// Kernel 4b: full-res conv + bilinear upsamples + gated mix.
// 8 blocks per (b,r) image (16 rows each), 256 threads.
// ---------------------------------------------------------------------------
__device__ __forceinline__ float up_bilin(const float* __restrict__ c, int S,
                                          int y, int x, float a, float off) {
    float py = a * (float)y + off;
    float px = a * (float)x + off;
    float fy = floorf(py), fx = floorf(px);
    float wy = py - fy, wx = px - fx;
    int y0 = (int)fy, x0 = (int)fx;
    int y1 = y0 + 1, x1 = x0 + 1;
    y0 = max(0, min(S - 1, y0)); y1 = max(0, min(S - 1, y1));
    x0 = max(0, min(S - 1, x0)); x1 = max(0, min(S - 1, x1));
    float v00 = c[y0 * S + x0], v01 = c[y0 * S + x1];
    float v10 = c[y1 * S + x0], v11 = c[y1 * S + x1];
    float v0 = v00 + wx * (v01 - v00);
    float v1 = v10 + wx * (v11 - v10);
    return v0 + wy * (v1 - v0);
}

__global__ void k_mix(const float* __restrict__ dwk,
                      const float* __restrict__ dwb) {
    __shared__ float s[18 * 128];                  // 16 output rows + halo
    int blk = blockIdx.x;                          // 0..191
    int br = blk >> 3, seg = blk & 7;
    int b = br / Rr, r = br - b * Rr;
    const float* img = g_xr + (long long)br * Nn;
    float* outp = g_mixed + (long long)br * Nn;
    const float* c64 = g_c64 + br * 64 * 64;
    const float* c32 = g_c32 + br * 32 * 32;
    const float* c16 = g_c16 + br * 16 * 16;

    int y0 = seg * 16;
    int t = threadIdx.x;
    for (int i = t; i < 18 * 128; i += 256) {
        int ry = y0 - 1 + (i >> 7);
        s[i] = (ry >= 0 && ry < 128) ? img[ry * 128 + (i & 127)] : 0.f;
    }
    __syncthreads();

    float k9[9];
#pragma unroll
    for (int i = 0; i < 9; i++) k9[i] = dwk[r * 9 + i];
    float kb = dwb[r];
    float G0 = g_G[b * NE + 0], G1 = g_G[b * NE + 1];
    float G2 = g_G[b * NE + 2], G3 = g_G[b * NE + 3];

#pragma unroll
    for (int it = 0; it < 8; it++) {
        int i = it * 256 + t;                      // 0..2047
        int yy = i >> 7, x = i & 127;
        int y = y0 + yy;
        const float* srow = s + yy * 128;          // smem row for (y-1)
        float v = kb;
#pragma unroll
        for (int ky = 0; ky < 3; ky++) {
            const float* rr = srow + ky * 128;
#pragma unroll
            for (int kx = 0; kx < 3; kx++) {
                int xx = x + kx - 1;
                if (xx < 0 || xx >= 128) continue;
                v += rr[xx] * k9[ky * 3 + kx];
            }
        }
        float u1 = up_bilin(c64, 64, y, x, 0.5f,   -0.25f);
        float u2 = up_bilin(c32, 32, y, x, 0.25f,  -0.375f);
        float u3 = up_bilin(c16, 16, y, x, 0.125f, -0.4375f);
        outp[y * 128 + x] = G0 * v + G1 * u1 + G2 * u2 + G3 * u3;
    }
}

// ---------------------------------------------------------------------------
// Kernel 5: out = x + mixed @ Wu + bu.  192 threads = one row of float4;
// 8 rows per block so Wu/bu stay in registers.
// ---------------------------------------------------------------------------
__global__ void k_out(const float* __restrict__ x,
                      const float* __restrict__ Wu,
                      const float* __restrict__ bu,
                      float* __restrict__ out) {
    int t = threadIdx.x;  // 0..191
    const float4* Wu4 = (const float4*)Wu;
    float4 w0 = Wu4[t], w1 = Wu4[192 + t], w2 = Wu4[384 + t];
    float4 bv = ((const float4*)bu)[t];

    long long row0 = (long long)blockIdx.x * 8;
#pragma unroll
    for (int i = 0; i < 8; i++) {
        long long row = row0 + i;
        int b = (int)(row >> 14), n = (int)(row & (Nn - 1));
        float m0 = g_mixed[((long long)b * Rr + 0) * Nn + n];
        float m1 = g_mixed[((long long)b * Rr + 1) * Nn + n];
        float m2 = g_mixed[((long long)b * Rr + 2) * Nn + n];
        float4 xv = ((const float4*)(x + row * Dd))[t];
        float4 rv;
        rv.x = xv.x + m0 * w0.x + m1 * w1.x + m2 * w2.x + bv.x;
        rv.y = xv.y + m0 * w0.y + m1 * w1.y + m2 * w2.y + bv.y;
        rv.z = xv.z + m0 * w0.z + m1 * w1.z + m2 * w2.z + bv.z;
        rv.w = xv.w + m0 * w0.w + m1 * w1.w + m2 * w2.w + bv.w;
        ((float4*)out)[row * 192 + t] = rv;
    }
}

// ---------------------------------------------------------------------------
extern "C" void kernel_launch(void* const* d_in, const int* in_sizes, int n_in,
                              void* d_out, int out_size) {
    const float* x     = (const float*)d_in[0];
    const float* noise = (const float*)d_in[1];
    const float* Wd    = (const float*)d_in[2];
    const float* bd    = (const float*)d_in[3];
    const float* Wu    = (const float*)d_in[4];
    const float* bu    = (const float*)d_in[5];
    const float* Wg    = (const float*)d_in[6];
    const float* Wn    = (const float*)d_in[7];
    const float* dwk   = (const float*)d_in[8];
    const float* dwb   = (const float*)d_in[9];
    float* out = (float*)d_out;

    k_proj_down<<<(Bb * Nn) / 8, 256>>>(x, Wd, bd);
    k_pyramid<<<Bb * Rr, 256>>>(dwk, dwb);       // independent of mean/gate
    k_mean<<<Bb * Rr, 256>>>();
    k_gate<<<1, 32>>>(noise, Wg, Wn);
    k_mix<<<Bb * Rr * 8, 256>>>(dwk, dwb);
    k_out<<<(Bb * Nn) / 8, 192>>>(x, Wu, bu, out);
}